// round 4
// baseline (speedup 1.0000x reference)
#include <cuda_runtime.h>
#include <cuda_bf16.h>
#include <cstdint>

// Problem constants
#define G 8
#define T 4096
#define H 2048
#define E 64
#define GT (G*T)              // 32768 tokens

// Output layout (float32, concatenated in reference return order)
#define DI_OFF 0              // dispatch_indices [G,T,2,2] -> 131072
#define CW_OFF 131072         // combine_weights  [G,T,2]   -> 65536
#define AUX_OFF 196608        // scalar
#define P_OFF 196609          // router_probs [G,T,64] -> 2097152
#define Z_OFF 2293761         // scalar

// K1 tiling
#define KC 16                 // k-chunk
#define NC (H/KC)             // 128 chunks
#define TM 128                // tokens per CTA
#define NCTA (GT/TM)          // 256 CTAs

// -------- scratch (device globals; no allocation allowed) --------
__device__ float g_gate0[GT];
__device__ float g_gate1[GT];
__device__ int   g_e0[GT];
__device__ int   g_e1[GT];
__device__ int   g_sorted[GT];
__device__ int   g_prio0[GT];
__device__ int   g_prio1[GT];
__device__ float g_zpart[NCTA];
__device__ int   g_cnt[G*E];
__device__ float g_psum2[G*8*E];

#define FMA2(a, x, w) asm("fma.rn.f32x2 %0, %1, %2, %0;" : "+l"(a) : "l"(x), "l"(w))

// ---------------- K0: zero the atomic counters ----------------
__global__ void k0_zero() {
    int i = blockIdx.x * blockDim.x + threadIdx.x;
    if (i < G*E) g_cnt[i] = 0;
}

// ---------------- K1: GEMM + softmax + top2 + z partials ----------------
// 128 tokens/CTA, 128 threads. Thread (r=tid>>3, c=tid&7) computes tokens
// r*8..r*8+7 x experts c*8..c*8+7 as 32 f32x2 accumulators (token pairs).
// W stored PRE-DUPLICATED in smem ([w,w,w',w'] granules, permuted so the 4
// per-thread LDS.128 are bank-conflict-free) -> no MOV packing in the loop.
__global__ __launch_bounds__(128) void k1_gemm(
    const float* __restrict__ X, const float* __restrict__ W,
    const float* __restrict__ Bv, float* __restrict__ out)
{
    __shared__ __align__(16) float sm[8704];   // pipe: xs 2*2048 + ws 2*2048 = 8192; ls overlay 8704
    __shared__ float bs[64];
    __shared__ float zred[4];

    const int tid = threadIdx.x;
    const int r = tid >> 3, c = tid & 7;
    const int tok0 = blockIdx.x * TM;
    const int u  = tid >> 2;        // 0..31 (ldg token lane)
    const int h4 = tid & 3;         // 0..3  (ldg float4-in-chunk)

    if (tid < 64) bs[tid] = Bv[tid];

    unsigned long long acc[4][8];
#pragma unroll
    for (int tp = 0; tp < 4; ++tp)
#pragma unroll
        for (int j = 0; j < 8; ++j) acc[tp][j] = 0ULL;

    const float4* Wv4 = reinterpret_cast<const float4*>(W);

    float4 xr[4], wr[2];

    // ---- LDG chunk ch into regs ----
    auto ldg_chunk = [&](int ch) {
        const int hc = ch * KC;
#pragma unroll
        for (int p = 0; p < 4; ++p) {
            int tk = p*32 + u;
            xr[p] = *reinterpret_cast<const float4*>(
                &X[(size_t)(tok0 + tk)*H + hc + h4*4]);
        }
#pragma unroll
        for (int p = 0; p < 2; ++p) {
            int i = p*128 + tid;
            wr[p] = Wv4[(size_t)(hc + (i >> 4))*16 + (i & 15)];
        }
    };

    // ---- STS regs into buffer b ----
    auto sts_chunk = [&](int b) {
        float* xsb = &sm[b * (KC*TM)];
#pragma unroll
        for (int p = 0; p < 4; ++p) {
            int tk = p*32 + u;
            int xb = tk ^ (h4*8);                    // xor swizzle (bank-free)
            xsb[(h4*4 + 0)*TM + xb] = xr[p].x;
            xsb[(h4*4 + 1)*TM + xb] = xr[p].y;
            xsb[(h4*4 + 2)*TM + xb] = xr[p].z;
            xsb[(h4*4 + 3)*TM + xb] = xr[p].w;
        }
        // W duplicated: row h has 32 granules of 4 floats [w(e),w(e),w(e+1),w(e+1)]
        // logical granule gl (experts 2gl,2gl+1) at physical slot (gl&3)*8 + (gl>>2)
        float* wsb = &sm[2*(KC*TM) + b*(KC*128)];
#pragma unroll
        for (int p = 0; p < 2; ++p) {
            int i = p*128 + tid;
            int h = i >> 4, g = i & 15;              // g-th float4 = experts 4g..4g+3
            int s0 = ((g & 1) << 4) + (g >> 1);      // slot of granule 2g
            float4 v = wr[p];
            *reinterpret_cast<float4*>(&wsb[h*128 + s0*4])
                = make_float4(v.x, v.x, v.y, v.y);
            *reinterpret_cast<float4*>(&wsb[h*128 + (s0+8)*4])
                = make_float4(v.z, v.z, v.w, v.w);
        }
    };

    // ---- compute chunk from buffer b ----
    auto comp_chunk = [&](int b) {
        const float* xsb = &sm[b * (KC*TM)];
        const float* wsb = &sm[2*(KC*TM) + b*(KC*128)];
#pragma unroll
        for (int h = 0; h < KC; ++h) {
            int s = h >> 2;
            const float* xp = &xsb[h*TM + (((r ^ s) & 15) << 3)];
            ulonglong2 xA = *reinterpret_cast<const ulonglong2*>(xp);
            ulonglong2 xB = *reinterpret_cast<const ulonglong2*>(xp + 4);
            // quarter q -> slot q*8+c -> experts c*8+2q, c*8+2q+1 (duplicated)
            const float* wp = &wsb[h*128 + c*4];
            ulonglong2 wq0 = *reinterpret_cast<const ulonglong2*>(wp);
            ulonglong2 wq1 = *reinterpret_cast<const ulonglong2*>(wp + 32);
            ulonglong2 wq2 = *reinterpret_cast<const ulonglong2*>(wp + 64);
            ulonglong2 wq3 = *reinterpret_cast<const ulonglong2*>(wp + 96);
            unsigned long long wd[8] = {wq0.x, wq0.y, wq1.x, wq1.y,
                                        wq2.x, wq2.y, wq3.x, wq3.y};
            unsigned long long xp2[4] = {xA.x, xA.y, xB.x, xB.y};
#pragma unroll
            for (int tp = 0; tp < 4; ++tp)
#pragma unroll
                for (int j = 0; j < 8; ++j)
                    FMA2(acc[tp][j], xp2[tp], wd[j]);
        }
    };

    ldg_chunk(0);
    sts_chunk(0);
    for (int ch = 0; ch < NC; ++ch) {
        if (ch + 1 < NC) ldg_chunk(ch + 1);
        __syncthreads();                 // buffer (ch&1) fully written by all warps
        comp_chunk(ch & 1);
        if (ch + 1 < NC) sts_chunk((ch + 1) & 1);
    }
    __syncthreads();

    // ---- dump accumulators to ls[128][68] ----
#pragma unroll
    for (int tp = 0; tp < 4; ++tp)
#pragma unroll
        for (int j = 0; j < 8; ++j) {
            int t = r*8 + tp*2, e = c*8 + j;
            unsigned long long a = acc[tp][j];
            sm[t*68 + e]     = __uint_as_float((unsigned)(a & 0xffffffffULL));
            sm[(t+1)*68 + e] = __uint_as_float((unsigned)(a >> 32));
        }
    __syncthreads();

    // ---- per-token epilogue (1 token per thread) ----
    const int t = tid;
    float lg[64];
#pragma unroll
    for (int e = 0; e < 64; ++e) lg[e] = sm[t*68 + e] + bs[e];

    float mx = lg[0];
#pragma unroll
    for (int e = 1; e < 64; ++e) mx = fmaxf(mx, lg[e]);
    float ssum = 0.f;
#pragma unroll
    for (int e = 0; e < 64; ++e) { float p = expf(lg[e] - mx); lg[e] = p; ssum += p; }
    float logz = mx + logf(ssum);
    float inv  = 1.f / ssum;
#pragma unroll
    for (int e = 0; e < 64; ++e) lg[e] *= inv;

    float p0 = -1.f, p1 = -1.f; int i0 = 0, i1 = 0;
#pragma unroll
    for (int e = 0; e < 64; ++e) {
        float v = lg[e];
        if (v > p0) { p1 = p0; i1 = i0; p0 = v; i0 = e; }
        else if (v > p1) { p1 = v; i1 = e; }
    }

    const int token = tok0 + t;
    g_gate0[token] = p0; g_gate1[token] = p1;
    g_e0[token] = i0;    g_e1[token] = i1;
    const int grp = token >> 12;
    atomicAdd(&g_cnt[grp*E + i0], 1);
    atomicAdd(&g_cnt[grp*E + i1], 1);

    // probs back to ls, then coalesced scalar copy-out (P base is 4B-aligned only)
#pragma unroll
    for (int e = 0; e < 64; ++e) sm[t*68 + e] = lg[e];

    // z partial (4 warps)
    float zl = logz * logz;
#pragma unroll
    for (int o = 16; o; o >>= 1) zl += __shfl_xor_sync(0xffffffffu, zl, o);
    if ((tid & 31) == 0) zred[tid >> 5] = zl;
    __syncthreads();

    float* P = out + P_OFF + (size_t)tok0*64;
    for (int k = tid; k < TM*64; k += 128) P[k] = sm[(k >> 6)*68 + (k & 63)];

    if (tid == 0)
        g_zpart[blockIdx.x] = zred[0] + zred[1] + zred[2] + zred[3];
}

// ---------------- K2: stable rank by gate0 (descending) ----------------
__global__ __launch_bounds__(256) void k2_rank() {
    __shared__ float gs[T];
    const int tid = threadIdx.x;
    const int grp = blockIdx.y;
    for (int i = tid; i < T; i += 256) gs[i] = g_gate0[grp*T + i];
    __syncthreads();
    const int t = blockIdx.x * 256 + tid;
    const float gi = gs[t];
    int rank = 0;
#pragma unroll 8
    for (int j = 0; j < T; ++j) {
        float gj = gs[j];
        rank += (gj > gi) || (gj == gi && j < t);
    }
    g_sorted[grp*T + rank] = t;
}

// ---------------- K3: expert buffer priorities + dispatch/combine ----------------
// 1024 threads; 32 warps each own a contiguous 256-entry segment of the 8192-entry
// (k-major, rank-ordered) sequence. Warp-local running counts (counters zeroed by
// the OWNING warp -> no cross-warp race), then one exclusive scan over warp
// histograms, then scatter.
__global__ __launch_bounds__(1024) void k3_prio(float* __restrict__ out, const int* __restrict__ capPtr) {
    __shared__ unsigned char se[2*T];      // expert id per sequence entry
    __shared__ unsigned char soff[2*T];    // local offset within warp segment (<256)
    __shared__ int wcnt[32][64];           // per-warp per-expert counts
    __shared__ int wbase[32][64];          // exclusive scan over warps

    const int tid = threadIdx.x;
    const int grp = blockIdx.x;
    const int cap = capPtr ? *capPtr : 160;
    const int w = tid >> 5, lane = tid & 31;
    const unsigned lt = (1u << lane) - 1u;

    // each warp zeros ITS OWN counters (warp-local, no barrier needed)
    wcnt[w][lane] = 0;
    wcnt[w][lane + 32] = 0;

    // each warp loads its own 256-entry segment (no cross-warp dependency)
#pragma unroll
    for (int i = 0; i < 8; ++i) {
        int p = w*256 + i*32 + lane;
        int tok = g_sorted[grp*T + (p & (T-1))];
        se[p] = (unsigned char)((p < T) ? g_e0[grp*T + tok] : g_e1[grp*T + tok]);
    }
    __syncwarp();

    // warp-sequential running counts over the 8 sub-chunks
#pragma unroll
    for (int i = 0; i < 8; ++i) {
        int p = w*256 + i*32 + lane;
        int e = se[p];
        unsigned m = __match_any_sync(0xffffffffu, e);
        int lrank = __popc(m & lt);
        int off = wcnt[w][e] + lrank;
        soff[p] = (unsigned char)off;
        __syncwarp();
        if (lane == (__ffs(m) - 1)) wcnt[w][e] += __popc(m);
        __syncwarp();
    }
    __syncthreads();

    // exclusive scan over warps, per expert (64 threads, 32 steps)
    if (tid < 64) {
        int run = 0;
#pragma unroll
        for (int ww = 0; ww < 32; ++ww) {
            wbase[ww][tid] = run;
            run += wcnt[ww][tid];
        }
    }
    __syncthreads();

    // scatter priorities back to token order
#pragma unroll
    for (int i = 0; i < 8; ++i) {
        int p = i*1024 + tid;
        int prio = wbase[p >> 8][se[p]] + soff[p];
        int tok = g_sorted[grp*T + (p & (T-1))];
        if (p < T) g_prio0[grp*T + tok] = prio; else g_prio1[grp*T + tok] = prio;
    }
    __syncthreads();

    // final per-token outputs for this group
    for (int t = tid; t < T; t += 1024) {
        int idx = grp*T + t;
        int e0 = g_e0[idx], e1 = g_e1[idx];
        int pr0 = g_prio0[idx], pr1 = g_prio1[idx];
        float gt0 = g_gate0[idx], gt1 = g_gate1[idx];
        float4 d = make_float4((float)e0, (float)pr0, (float)e1, (float)pr1);
        reinterpret_cast<float4*>(out + DI_OFF)[idx] = d;
        float2 cc = make_float2(pr0 < cap ? gt0 : 0.f, pr1 < cap ? gt1 : 0.f);
        reinterpret_cast<float2*>(out + CW_OFF)[idx] = cc;
    }
}

// ---------------- K4: deterministic per-(g,chunk,e) prob partial sums ----------------
__global__ __launch_bounds__(256) void k4_psum(const float* __restrict__ out) {
    const float* P = out + P_OFF;
    const int grp = blockIdx.x;
    const int ch  = blockIdx.y;
    const int e = threadIdx.x & 63;
    const int q = threadIdx.x >> 6;
    float s = 0.f;
    const int t0 = ch * 512;
    for (int t = t0 + q; t < t0 + 512; t += 4)
        s += P[(size_t)(grp*T + t)*64 + e];
    __shared__ float smr[4][64];
    smr[q][e] = s;
    __syncthreads();
    if (threadIdx.x < 64)
        g_psum2[(grp*8 + ch)*64 + threadIdx.x] =
            smr[0][threadIdx.x] + smr[1][threadIdx.x] +
            smr[2][threadIdx.x] + smr[3][threadIdx.x];
}

// ---------------- K5: final scalars ----------------
__global__ void k5_final(float* __restrict__ out) {
    int lane = threadIdx.x;
    float a = 0.f;
    for (int e = lane; e < 64; e += 32)
        for (int g = 0; g < G; ++g) {
            float ps = 0.f;
#pragma unroll
            for (int ch = 0; ch < 8; ++ch) ps += g_psum2[(g*8 + ch)*64 + e];
            a += (float)g_cnt[g*E + e] * ps;
        }
#pragma unroll
    for (int o = 16; o; o >>= 1) a += __shfl_xor_sync(0xffffffffu, a, o);
    if (lane == 0) {
        float z = 0.f;
        for (int i = 0; i < NCTA; ++i) z += g_zpart[i];
        out[AUX_OFF] = a * (1.f / 2097152.f);
        out[Z_OFF]   = z * (1.f / 32768.f);
    }
}

extern "C" void kernel_launch(void* const* d_in, const int* in_sizes, int n_in,
                              void* d_out, int out_size) {
    const float* X = (const float*)d_in[0];
    const float* W = (const float*)d_in[1];
    const float* B = (const float*)d_in[2];
    const int* cap = (n_in > 3) ? (const int*)d_in[3] : nullptr;
    float* out = (float*)d_out;

    k0_zero<<<1, 512>>>();
    k1_gemm<<<NCTA, 128>>>(X, W, B, out);
    k2_rank<<<dim3(16, 8), 256>>>();
    k3_prio<<<G, 1024>>>(out, cap);
    k4_psum<<<dim3(8, 8), 256>>>(out);
    k5_final<<<1, 32>>>(out);
}

// round 5
// speedup vs baseline: 1.1308x; 1.1308x over previous
#include <cuda_runtime.h>
#include <cuda_bf16.h>
#include <cstdint>

// Problem constants
#define G 8
#define T 4096
#define H 2048
#define E 64
#define GT (G*T)              // 32768 tokens

// Output layout (float32, concatenated in reference return order)
#define DI_OFF 0              // dispatch_indices [G,T,2,2] -> 131072
#define CW_OFF 131072         // combine_weights  [G,T,2]   -> 65536
#define AUX_OFF 196608        // scalar
#define P_OFF 196609          // router_probs [G,T,64] -> 2097152
#define Z_OFF 2293761         // scalar

// K1 tiling
#define KC 16                 // k-chunk
#define NC (H/KC)             // 128 chunks
#define TM 128                // tokens per CTA
#define NCTA (GT/TM)          // 256 CTAs

// -------- scratch (device globals; no allocation allowed) --------
__device__ float g_gate0[GT];
__device__ float g_gate1[GT];
__device__ int   g_e0[GT];
__device__ int   g_e1[GT];
__device__ int   g_sorted[GT];
__device__ int   g_prio0[GT];
__device__ int   g_prio1[GT];
__device__ float g_zpart[NCTA];
__device__ int   g_cnt[G*E];
__device__ float g_psum2[G*8*E];

#define DUP64(d, f) asm("mov.b64 %0, {%1, %1};" : "=l"(d) : "r"(__float_as_uint(f)))
#define FMA2(a, x, w) asm("fma.rn.f32x2 %0, %1, %2, %0;" : "+l"(a) : "l"(x), "l"(w))

// ---------------- K0: zero the atomic counters ----------------
__global__ void k0_zero() {
    int i = blockIdx.x * blockDim.x + threadIdx.x;
    if (i < G*E) g_cnt[i] = 0;
}

// ---------------- K1: GEMM + softmax + top2 + z partials ----------------
// 128 tokens/CTA, 128 threads. Thread (r=tid>>3, c=tid&7) computes tokens
// r*8..r*8+7 x experts c*8..c*8+7.
// EXPERT-PAIR accumulators: acc[t][j] = f32x2 logits (e=c*8+2j, c*8+2j+1).
// W kept plain in smem (granule-permuted, conflict-free) and read directly as
// f32x2 operands; only x is broadcast-duplicated (8 register MOVs/h-step).
// Per h-step: 4 LDS.128 (conflict-free) + 8 MOV + 32 FFMA2 -> FMA-pipe bound.
__global__ __launch_bounds__(128) void k1_gemm(
    const float* __restrict__ X, const float* __restrict__ W,
    const float* __restrict__ Bv, float* __restrict__ out)
{
    __shared__ __align__(16) float sm[8704];   // pipe: xs 2*2048 + ws 2*1024 = 6144; ls overlay 8704
    __shared__ float bs[64];
    __shared__ float zred[4];

    const int tid = threadIdx.x;
    const int r = tid >> 3, c = tid & 7;
    const int tok0 = blockIdx.x * TM;
    const int u  = tid >> 2;        // 0..31 (ldg token lane)
    const int h4 = tid & 3;         // 0..3  (ldg float4-in-chunk)

    if (tid < 64) bs[tid] = Bv[tid];

    unsigned long long acc[8][4];
#pragma unroll
    for (int t = 0; t < 8; ++t)
#pragma unroll
        for (int j = 0; j < 4; ++j) acc[t][j] = 0ULL;

    const float4* Wv4 = reinterpret_cast<const float4*>(W);

    float4 xr[4], wr[2];

    // ---- LDG chunk ch into regs ----
    auto ldg_chunk = [&](int ch) {
        const int hc = ch * KC;
#pragma unroll
        for (int p = 0; p < 4; ++p) {
            int tk = p*32 + u;
            xr[p] = *reinterpret_cast<const float4*>(
                &X[(size_t)(tok0 + tk)*H + hc + h4*4]);
        }
#pragma unroll
        for (int p = 0; p < 2; ++p) {
            int i = p*128 + tid;
            wr[p] = Wv4[(size_t)(hc + (i >> 4))*16 + (i & 15)];
        }
    };

    // ---- STS regs into buffer b ----
    auto sts_chunk = [&](int b) {
        float* xsb = &sm[b * (KC*TM)];
#pragma unroll
        for (int p = 0; p < 4; ++p) {
            int tk = p*32 + u;
            int xb = tk ^ (h4*8);                    // xor swizzle (bank-free)
            xsb[(h4*4 + 0)*TM + xb] = xr[p].x;
            xsb[(h4*4 + 1)*TM + xb] = xr[p].y;
            xsb[(h4*4 + 2)*TM + xb] = xr[p].z;
            xsb[(h4*4 + 3)*TM + xb] = xr[p].w;
        }
        // W plain: row h = 16 granules of 4 floats; granule g (experts 4g..4g+3)
        // stored at slot ((g&1)<<3)+(g>>1) -> both comp reads conflict-free
        float* wsb = &sm[2*(KC*TM) + b*(KC*64)];
#pragma unroll
        for (int p = 0; p < 2; ++p) {
            int i = p*128 + tid;
            int h = i >> 4, g = i & 15;
            int slot = ((g & 1) << 3) + (g >> 1);
            *reinterpret_cast<float4*>(&wsb[h*64 + slot*4]) = wr[p];
        }
    };

    // ---- compute chunk from buffer b ----
    auto comp_chunk = [&](int b) {
        const float* xsb = &sm[b * (KC*TM)];
        const float* wsb = &sm[2*(KC*TM) + b*(KC*64)];
#pragma unroll
        for (int h = 0; h < KC; ++h) {
            int s = h >> 2;
            const float* xp = &xsb[h*TM + (((r ^ s) & 15) << 3)];
            float4 xa = *reinterpret_cast<const float4*>(xp);
            float4 xb = *reinterpret_cast<const float4*>(xp + 4);
            // slot c = granule 2c (experts 8c..8c+3); slot 8+c = granule 2c+1
            const float* wp = &wsb[h*64 + c*4];
            ulonglong2 wA = *reinterpret_cast<const ulonglong2*>(wp);       // pairs j=0,1
            ulonglong2 wB = *reinterpret_cast<const ulonglong2*>(wp + 32);  // pairs j=2,3
            unsigned long long wv[4] = {wA.x, wA.y, wB.x, wB.y};
            unsigned long long xd[8];
            DUP64(xd[0], xa.x); DUP64(xd[1], xa.y); DUP64(xd[2], xa.z); DUP64(xd[3], xa.w);
            DUP64(xd[4], xb.x); DUP64(xd[5], xb.y); DUP64(xd[6], xb.z); DUP64(xd[7], xb.w);
#pragma unroll
            for (int t = 0; t < 8; ++t)
#pragma unroll
                for (int j = 0; j < 4; ++j)
                    FMA2(acc[t][j], xd[t], wv[j]);
        }
    };

    ldg_chunk(0);
    sts_chunk(0);
    for (int ch = 0; ch < NC; ++ch) {
        if (ch + 1 < NC) ldg_chunk(ch + 1);
        __syncthreads();                 // buffer (ch&1) fully written by all warps
        comp_chunk(ch & 1);
        if (ch + 1 < NC) sts_chunk((ch + 1) & 1);
    }
    __syncthreads();

    // ---- dump accumulators to ls[128][68] ----
#pragma unroll
    for (int t = 0; t < 8; ++t)
#pragma unroll
        for (int j = 0; j < 4; ++j) {
            int tok = r*8 + t, e = c*8 + 2*j;
            unsigned long long a = acc[t][j];
            sm[tok*68 + e]     = __uint_as_float((unsigned)(a & 0xffffffffULL));
            sm[tok*68 + e + 1] = __uint_as_float((unsigned)(a >> 32));
        }
    __syncthreads();

    // ---- per-token epilogue (1 token per thread) ----
    const int t = tid;
    float lg[64];
#pragma unroll
    for (int e = 0; e < 64; ++e) lg[e] = sm[t*68 + e] + bs[e];

    float mx = lg[0];
#pragma unroll
    for (int e = 1; e < 64; ++e) mx = fmaxf(mx, lg[e]);
    float ssum = 0.f;
#pragma unroll
    for (int e = 0; e < 64; ++e) { float p = expf(lg[e] - mx); lg[e] = p; ssum += p; }
    float logz = mx + logf(ssum);
    float inv  = 1.f / ssum;
#pragma unroll
    for (int e = 0; e < 64; ++e) lg[e] *= inv;

    float p0 = -1.f, p1 = -1.f; int i0 = 0, i1 = 0;
#pragma unroll
    for (int e = 0; e < 64; ++e) {
        float v = lg[e];
        if (v > p0) { p1 = p0; i1 = i0; p0 = v; i0 = e; }
        else if (v > p1) { p1 = v; i1 = e; }
    }

    const int token = tok0 + t;
    g_gate0[token] = p0; g_gate1[token] = p1;
    g_e0[token] = i0;    g_e1[token] = i1;
    const int grp = token >> 12;
    atomicAdd(&g_cnt[grp*E + i0], 1);
    atomicAdd(&g_cnt[grp*E + i1], 1);

    // probs back to ls, then coalesced scalar copy-out (P base is 4B-aligned only)
#pragma unroll
    for (int e = 0; e < 64; ++e) sm[t*68 + e] = lg[e];

    // z partial (4 warps)
    float zl = logz * logz;
#pragma unroll
    for (int o = 16; o; o >>= 1) zl += __shfl_xor_sync(0xffffffffu, zl, o);
    if ((tid & 31) == 0) zred[tid >> 5] = zl;
    __syncthreads();

    float* P = out + P_OFF + (size_t)tok0*64;
    for (int k = tid; k < TM*64; k += 128) P[k] = sm[(k >> 6)*68 + (k & 63)];

    if (tid == 0)
        g_zpart[blockIdx.x] = zred[0] + zred[1] + zred[2] + zred[3];
}

// ---------------- K2: stable rank by gate0 (descending) ----------------
__global__ __launch_bounds__(256) void k2_rank() {
    __shared__ float gs[T];
    const int tid = threadIdx.x;
    const int grp = blockIdx.y;
    for (int i = tid; i < T; i += 256) gs[i] = g_gate0[grp*T + i];
    __syncthreads();
    const int t = blockIdx.x * 256 + tid;
    const float gi = gs[t];
    int rank = 0;
#pragma unroll 8
    for (int j = 0; j < T; ++j) {
        float gj = gs[j];
        rank += (gj > gi) || (gj == gi && j < t);
    }
    g_sorted[grp*T + rank] = t;
}

// ---------------- K3: expert buffer priorities + dispatch/combine ----------------
// 1024 threads; 32 warps each own a contiguous 256-entry segment of the 8192-entry
// (k-major, rank-ordered) sequence. Warp-local running counts (counters zeroed by
// the OWNING warp -> no cross-warp race), then one exclusive scan over warp
// histograms, then scatter.
__global__ __launch_bounds__(1024) void k3_prio(float* __restrict__ out, const int* __restrict__ capPtr) {
    __shared__ unsigned char se[2*T];      // expert id per sequence entry
    __shared__ unsigned char soff[2*T];    // local offset within warp segment (<256)
    __shared__ int wcnt[32][64];           // per-warp per-expert counts
    __shared__ int wbase[32][64];          // exclusive scan over warps

    const int tid = threadIdx.x;
    const int grp = blockIdx.x;
    const int cap = capPtr ? *capPtr : 160;
    const int w = tid >> 5, lane = tid & 31;
    const unsigned lt = (1u << lane) - 1u;

    // each warp zeros ITS OWN counters (warp-local, no barrier needed)
    wcnt[w][lane] = 0;
    wcnt[w][lane + 32] = 0;

    // each warp loads its own 256-entry segment (no cross-warp dependency)
#pragma unroll
    for (int i = 0; i < 8; ++i) {
        int p = w*256 + i*32 + lane;
        int tok = g_sorted[grp*T + (p & (T-1))];
        se[p] = (unsigned char)((p < T) ? g_e0[grp*T + tok] : g_e1[grp*T + tok]);
    }
    __syncwarp();

    // warp-sequential running counts over the 8 sub-chunks
#pragma unroll
    for (int i = 0; i < 8; ++i) {
        int p = w*256 + i*32 + lane;
        int e = se[p];
        unsigned m = __match_any_sync(0xffffffffu, e);
        int lrank = __popc(m & lt);
        int off = wcnt[w][e] + lrank;
        soff[p] = (unsigned char)off;
        __syncwarp();
        if (lane == (__ffs(m) - 1)) wcnt[w][e] += __popc(m);
        __syncwarp();
    }
    __syncthreads();

    // exclusive scan over warps, per expert (64 threads, 32 steps)
    if (tid < 64) {
        int run = 0;
#pragma unroll
        for (int ww = 0; ww < 32; ++ww) {
            wbase[ww][tid] = run;
            run += wcnt[ww][tid];
        }
    }
    __syncthreads();

    // scatter priorities back to token order
#pragma unroll
    for (int i = 0; i < 8; ++i) {
        int p = i*1024 + tid;
        int prio = wbase[p >> 8][se[p]] + soff[p];
        int tok = g_sorted[grp*T + (p & (T-1))];
        if (p < T) g_prio0[grp*T + tok] = prio; else g_prio1[grp*T + tok] = prio;
    }
    __syncthreads();

    // final per-token outputs for this group
    for (int t = tid; t < T; t += 1024) {
        int idx = grp*T + t;
        int e0 = g_e0[idx], e1 = g_e1[idx];
        int pr0 = g_prio0[idx], pr1 = g_prio1[idx];
        float gt0 = g_gate0[idx], gt1 = g_gate1[idx];
        float4 d = make_float4((float)e0, (float)pr0, (float)e1, (float)pr1);
        reinterpret_cast<float4*>(out + DI_OFF)[idx] = d;
        float2 cc = make_float2(pr0 < cap ? gt0 : 0.f, pr1 < cap ? gt1 : 0.f);
        reinterpret_cast<float2*>(out + CW_OFF)[idx] = cc;
    }
}

// ---------------- K4: deterministic per-(g,chunk,e) prob partial sums ----------------
__global__ __launch_bounds__(256) void k4_psum(const float* __restrict__ out) {
    const float* P = out + P_OFF;
    const int grp = blockIdx.x;
    const int ch  = blockIdx.y;
    const int e = threadIdx.x & 63;
    const int q = threadIdx.x >> 6;
    float s = 0.f;
    const int t0 = ch * 512;
    for (int t = t0 + q; t < t0 + 512; t += 4)
        s += P[(size_t)(grp*T + t)*64 + e];
    __shared__ float smr[4][64];
    smr[q][e] = s;
    __syncthreads();
    if (threadIdx.x < 64)
        g_psum2[(grp*8 + ch)*64 + threadIdx.x] =
            smr[0][threadIdx.x] + smr[1][threadIdx.x] +
            smr[2][threadIdx.x] + smr[3][threadIdx.x];
}

// ---------------- K5: final scalars ----------------
__global__ void k5_final(float* __restrict__ out) {
    int lane = threadIdx.x;
    float a = 0.f;
    for (int e = lane; e < 64; e += 32)
        for (int g = 0; g < G; ++g) {
            float ps = 0.f;
#pragma unroll
            for (int ch = 0; ch < 8; ++ch) ps += g_psum2[(g*8 + ch)*64 + e];
            a += (float)g_cnt[g*E + e] * ps;
        }
#pragma unroll
    for (int o = 16; o; o >>= 1) a += __shfl_xor_sync(0xffffffffu, a, o);
    if (lane == 0) {
        float z = 0.f;
        for (int i = 0; i < NCTA; ++i) z += g_zpart[i];
        out[AUX_OFF] = a * (1.f / 2097152.f);
        out[Z_OFF]   = z * (1.f / 32768.f);
    }
}

extern "C" void kernel_launch(void* const* d_in, const int* in_sizes, int n_in,
                              void* d_out, int out_size) {
    const float* X = (const float*)d_in[0];
    const float* W = (const float*)d_in[1];
    const float* B = (const float*)d_in[2];
    const int* cap = (n_in > 3) ? (const int*)d_in[3] : nullptr;
    float* out = (float*)d_out;

    k0_zero<<<1, 512>>>();
    k1_gemm<<<NCTA, 128>>>(X, W, B, out);
    k2_rank<<<dim3(16, 8), 256>>>();
    k3_prio<<<G, 1024>>>(out, cap);
    k4_psum<<<dim3(8, 8), 256>>>(out);
    k5_final<<<1, 32>>>(out);
}

// round 8
// speedup vs baseline: 1.6415x; 1.4516x over previous
#include <cuda_runtime.h>
#include <cuda_fp16.h>
#include <cstdint>

// Problem constants
#define G 8
#define T 4096
#define H 2048
#define E 64
#define GT (G*T)              // 32768 tokens

// Output layout (float32, concatenated in reference return order)
#define DI_OFF 0              // dispatch_indices [G,T,2,2] -> 131072
#define CW_OFF 131072         // combine_weights  [G,T,2]   -> 65536
#define AUX_OFF 196608        // scalar
#define P_OFF 196609          // router_probs [G,T,64] -> 2097152
#define Z_OFF 2293761         // scalar

// K1 tiling
#define KB 64                 // k-elems per chunk (128B fp16 rows)
#define NCH (H/KB)            // 32 chunks
#define TM 128                // tokens per CTA
#define NCTA (GT/TM)          // 256 CTAs

// dynamic smem byte offsets
#define SO_BS   0                       // bias, 64 floats
#define SO_ZRED 256                     // 4 floats
#define SO_A1   1024                    // x hi limb: 2 bufs x 16KB
#define SO_A2   (SO_A1 + 32768)         // x lo limb: 2 bufs x 16KB
#define SO_B1   (SO_A2 + 32768)         // w hi limb: 2 bufs x 8KB
#define SO_B2   (SO_B1 + 16384)         // w lo limb: 2 bufs x 8KB
#define SMEM_TOTAL (SO_B2 + 16384)      // 99328 bytes
#define SO_LS   1024                    // epilogue overlay: 128 x 68 floats

// -------- scratch (device globals; no allocation allowed) --------
__device__ float g_gate0[GT];
__device__ float g_gate1[GT];
__device__ int   g_e0[GT];
__device__ int   g_e1[GT];
__device__ int   g_sorted[GT];
__device__ int   g_prio0[GT];
__device__ int   g_prio1[GT];
__device__ float g_zpart[NCTA];
__device__ int   g_cnt[G*E];
__device__ float g_psum2[G*8*E];
__device__ __half g_w1[E*H];   // W^T hi limb [expert][k]
__device__ __half g_w2[E*H];   // W^T lo limb

__device__ __forceinline__ uint32_t smem_u32(const void* p) {
    uint32_t a;
    asm("{ .reg .u64 t; cvta.to.shared.u64 t, %1; cvt.u32.u64 %0, t; }"
        : "=r"(a) : "l"(p));
    return a;
}
__device__ __forceinline__ void ldsm4(uint32_t* r, uint32_t a) {
    asm volatile("ldmatrix.sync.aligned.m8n8.x4.shared.b16 {%0,%1,%2,%3}, [%4];"
        : "=r"(r[0]), "=r"(r[1]), "=r"(r[2]), "=r"(r[3]) : "r"(a));
}
__device__ __forceinline__ void mma16816(float* c, const uint32_t* a, const uint32_t* b) {
    asm volatile("mma.sync.aligned.m16n8k16.row.col.f32.f16.f16.f32 "
        "{%0,%1,%2,%3}, {%4,%5,%6,%7}, {%8,%9}, {%0,%1,%2,%3};"
        : "+f"(c[0]), "+f"(c[1]), "+f"(c[2]), "+f"(c[3])
        : "r"(a[0]), "r"(a[1]), "r"(a[2]), "r"(a[3]), "r"(b[0]), "r"(b[1]));
}
__device__ __forceinline__ uint32_t h2u(__half2 h) {
    return *reinterpret_cast<uint32_t*>(&h);
}

// ---------------- K0: zero counters + preconvert W^T into fp16 limbs ----------------
__global__ __launch_bounds__(256) void k0_prep(const float* __restrict__ W) {
    int gidx = blockIdx.x * 256 + threadIdx.x;     // 128 CTAs -> 32768 threads
    if (gidx < G*E) g_cnt[gidx] = 0;
    // H*16 float4 granules: k = gidx>>4, experts 4q..4q+3
    int k = gidx >> 4, q = gidx & 15;
    float4 v = reinterpret_cast<const float4*>(W)[gidx];
    float xs[4] = {v.x, v.y, v.z, v.w};
#pragma unroll
    for (int j = 0; j < 4; ++j) {
        int e = 4*q + j;
        __half hi = __float2half_rn(xs[j]);
        float hf = __half2float(hi);
        __half lo = __float2half_rn(xs[j] - hf);
        g_w1[e*H + k] = hi;
        g_w2[e*H + k] = lo;
    }
}

// ---------------- K1: mma.sync GEMM (2-limb fp16) + softmax + top2 + z ----------------
// 256 threads (8 warps: 4 along M x 2 along N), 128 tokens/CTA, chunks of K=64.
// acc[mt][nt][4]: warp tile 32 tokens x 32 experts. 3 limb passes per k-step:
// x1*w1 + x1*w2 + x2*w1 (dropped x2*w2 ~ 2^-22 relative).
__global__ __launch_bounds__(256) void k1_gemm(
    const float* __restrict__ X, const float* __restrict__ Bv,
    float* __restrict__ out)
{
    extern __shared__ __align__(16) char smem[];
    const uint32_t sb = smem_u32(smem);
    const int tid = threadIdx.x;
    const int wid = tid >> 5, lane = tid & 31;
    const int wm = wid >> 1, wn = wid & 1;
    const int tok0 = blockIdx.x * TM;

    if (tid < 64) *reinterpret_cast<float*>(smem + SO_BS + tid*4) = Bv[tid];

    float acc[2][4][4];
#pragma unroll
    for (int mt = 0; mt < 2; ++mt)
#pragma unroll
        for (int nt = 0; nt < 4; ++nt)
#pragma unroll
            for (int i = 0; i < 4; ++i) acc[mt][nt][i] = 0.f;

    float4 xv[8];
    uint4 bv1[2], bv2[2];

    auto ldg_chunk = [&](int ch) {
        const int hc = ch * KB;
#pragma unroll
        for (int it = 0; it < 8; ++it) {
            int idx = it*256 + tid, row = idx >> 4, q = idx & 15;
            xv[it] = *reinterpret_cast<const float4*>(
                X + (size_t)(tok0 + row)*H + hc + q*4);
        }
#pragma unroll
        for (int it = 0; it < 2; ++it) {
            int idx = it*256 + tid, e = idx >> 3, g = idx & 7;
            bv1[it] = reinterpret_cast<const uint4*>(g_w1 + (size_t)e*H + hc)[g];
            bv2[it] = reinterpret_cast<const uint4*>(g_w2 + (size_t)e*H + hc)[g];
        }
    };

    auto sts_chunk = [&](int buf) {
        char* A1 = smem + SO_A1 + buf*16384;
        char* A2 = smem + SO_A2 + buf*16384;
#pragma unroll
        for (int it = 0; it < 8; ++it) {
            int idx = it*256 + tid, row = idx >> 4, q = idx & 15;
            float4 v = xv[it];
            __half2 h01 = __floats2half2_rn(v.x, v.y);
            __half2 h23 = __floats2half2_rn(v.z, v.w);
            float2 f01 = __half22float2(h01);
            float2 f23 = __half22float2(h23);
            __half2 l01 = __floats2half2_rn(v.x - f01.x, v.y - f01.y);
            __half2 l23 = __floats2half2_rn(v.z - f23.x, v.w - f23.y);
            int offs = row*128 + ((((q >> 1) ^ (row & 7)) << 4) | ((q & 1) << 3));
            *reinterpret_cast<uint2*>(A1 + offs) = make_uint2(h2u(h01), h2u(h23));
            *reinterpret_cast<uint2*>(A2 + offs) = make_uint2(h2u(l01), h2u(l23));
        }
        char* B1 = smem + SO_B1 + buf*8192;
        char* B2 = smem + SO_B2 + buf*8192;
#pragma unroll
        for (int it = 0; it < 2; ++it) {
            int idx = it*256 + tid, e = idx >> 3, g = idx & 7;
            int offs = e*128 + ((g ^ (e & 7)) << 4);
            *reinterpret_cast<uint4*>(B1 + offs) = bv1[it];
            *reinterpret_cast<uint4*>(B2 + offs) = bv2[it];
        }
    };

    auto comp_chunk = [&](int buf) {
        const uint32_t sA1 = sb + SO_A1 + buf*16384;
        const uint32_t sB1 = sb + SO_B1 + buf*8192;
#pragma unroll
        for (int ks = 0; ks < 4; ++ks) {
            const int kb = ks*2;
            uint32_t a1f[2][4], a2f[2][4], b1f[2][4], b2f[2][4];
#pragma unroll
            for (int mt = 0; mt < 2; ++mt) {
                int row = wm*32 + mt*16 + (lane & 15);
                int col = (kb + (lane >> 4)) ^ (row & 7);
                uint32_t ad = sA1 + row*128 + col*16;
                ldsm4(a1f[mt], ad);
                ldsm4(a2f[mt], ad + (SO_A2 - SO_A1));
            }
#pragma unroll
            for (int ng = 0; ng < 2; ++ng) {
                int rowb = wn*32 + ng*16 + (lane & 7) + ((lane >> 4) << 3);
                int colb = (kb + ((lane >> 3) & 1)) ^ (rowb & 7);
                uint32_t bd = sB1 + rowb*128 + colb*16;
                ldsm4(b1f[ng], bd);
                ldsm4(b2f[ng], bd + (SO_B2 - SO_B1));
            }
#pragma unroll
            for (int mt = 0; mt < 2; ++mt)
#pragma unroll
                for (int ng = 0; ng < 2; ++ng)
#pragma unroll
                    for (int hf = 0; hf < 2; ++hf) {
                        float* c = acc[mt][ng*2 + hf];
                        mma16816(c, a1f[mt], &b1f[ng][hf*2]);
                        mma16816(c, a1f[mt], &b2f[ng][hf*2]);
                        mma16816(c, a2f[mt], &b1f[ng][hf*2]);
                    }
        }
    };

    ldg_chunk(0);
    sts_chunk(0);
#pragma unroll 1
    for (int ch = 0; ch < NCH; ++ch) {
        if (ch + 1 < NCH) ldg_chunk(ch + 1);
        __syncthreads();
        comp_chunk(ch & 1);
        if (ch + 1 < NCH) sts_chunk((ch + 1) & 1);
    }
    __syncthreads();   // all comp done; safe to overlay ls

    // ---- dump accumulators to ls[128][68] ----
    float* ls = reinterpret_cast<float*>(smem + SO_LS);
#pragma unroll
    for (int mt = 0; mt < 2; ++mt)
#pragma unroll
        for (int nt = 0; nt < 4; ++nt) {
            int row = wm*32 + mt*16 + (lane >> 2);
            int col = wn*32 + nt*8 + (lane & 3)*2;
            *reinterpret_cast<float2*>(ls + row*68 + col) =
                make_float2(acc[mt][nt][0], acc[mt][nt][1]);
            *reinterpret_cast<float2*>(ls + (row + 8)*68 + col) =
                make_float2(acc[mt][nt][2], acc[mt][nt][3]);
        }
    __syncthreads();

    // ---- per-token epilogue (warps 0-3, 1 token per thread) ----
    float* bs = reinterpret_cast<float*>(smem + SO_BS);
    float* zred = reinterpret_cast<float*>(smem + SO_ZRED);
    float lg[64];
    float zl = 0.f;
    if (tid < 128) {
        const int t = tid;
#pragma unroll
        for (int e = 0; e < 64; ++e) lg[e] = ls[t*68 + e] + bs[e];

        float mx = lg[0];
#pragma unroll
        for (int e = 1; e < 64; ++e) mx = fmaxf(mx, lg[e]);
        float ssum = 0.f;
#pragma unroll
        for (int e = 0; e < 64; ++e) { float p = expf(lg[e] - mx); lg[e] = p; ssum += p; }
        float logz = mx + logf(ssum);
        float inv = 1.f / ssum;
#pragma unroll
        for (int e = 0; e < 64; ++e) lg[e] *= inv;

        float p0 = -1.f, p1 = -1.f; int i0 = 0, i1 = 0;
#pragma unroll
        for (int e = 0; e < 64; ++e) {
            float v = lg[e];
            if (v > p0) { p1 = p0; i1 = i0; p0 = v; i0 = e; }
            else if (v > p1) { p1 = v; i1 = e; }
        }
        const int token = tok0 + t;
        g_gate0[token] = p0; g_gate1[token] = p1;
        g_e0[token] = i0;    g_e1[token] = i1;
        const int grp = token >> 12;
        atomicAdd(&g_cnt[grp*E + i0], 1);
        atomicAdd(&g_cnt[grp*E + i1], 1);
        zl = logz * logz;
    }
    __syncthreads();

    if (tid < 128) {
        // probs back into ls
        float* row = ls + tid*68;
#pragma unroll
        for (int c = 0; c < 16; ++c)
            *reinterpret_cast<float4*>(row + c*4) =
                make_float4(lg[4*c], lg[4*c+1], lg[4*c+2], lg[4*c+3]);
#pragma unroll
        for (int o = 16; o; o >>= 1) zl += __shfl_xor_sync(0xffffffffu, zl, o);
        if (lane == 0) zred[wid] = zl;
    }
    __syncthreads();

    // coalesced prob copy-out (P base is only 4B-aligned), all 256 threads
    float* P = out + P_OFF + (size_t)tok0*64;
    for (int k = tid; k < TM*64; k += 256) P[k] = ls[(k >> 6)*68 + (k & 63)];

    if (tid == 0)
        g_zpart[blockIdx.x] = zred[0] + zred[1] + zred[2] + zred[3];
}

// ---------------- K2: stable rank by gate0 (descending) ----------------
__global__ __launch_bounds__(256) void k2_rank() {
    __shared__ float gs[T];
    const int tid = threadIdx.x;
    const int grp = blockIdx.y;
    for (int i = tid; i < T; i += 256) gs[i] = g_gate0[grp*T + i];
    __syncthreads();
    const int t = blockIdx.x * 256 + tid;
    const float gi = gs[t];
    int rank = 0;
#pragma unroll 8
    for (int j = 0; j < T; ++j) {
        float gj = gs[j];
        rank += (gj > gi) || (gj == gi && j < t);
    }
    g_sorted[grp*T + rank] = t;
}

// ---------------- K3: expert buffer priorities + dispatch/combine ----------------
__global__ __launch_bounds__(1024) void k3_prio(float* __restrict__ out, const int* __restrict__ capPtr) {
    __shared__ unsigned char se[2*T];
    __shared__ unsigned char soff[2*T];
    __shared__ int wcnt[32][64];
    __shared__ int wbase[32][64];

    const int tid = threadIdx.x;
    const int grp = blockIdx.x;
    const int cap = capPtr ? *capPtr : 160;
    const int w = tid >> 5, lane = tid & 31;
    const unsigned lt = (1u << lane) - 1u;

    wcnt[w][lane] = 0;
    wcnt[w][lane + 32] = 0;

#pragma unroll
    for (int i = 0; i < 8; ++i) {
        int p = w*256 + i*32 + lane;
        int tok = g_sorted[grp*T + (p & (T-1))];
        se[p] = (unsigned char)((p < T) ? g_e0[grp*T + tok] : g_e1[grp*T + tok]);
    }
    __syncwarp();

#pragma unroll
    for (int i = 0; i < 8; ++i) {
        int p = w*256 + i*32 + lane;
        int e = se[p];
        unsigned m = __match_any_sync(0xffffffffu, e);
        int lrank = __popc(m & lt);
        int off = wcnt[w][e] + lrank;
        soff[p] = (unsigned char)off;
        __syncwarp();
        if (lane == (__ffs(m) - 1)) wcnt[w][e] += __popc(m);
        __syncwarp();
    }
    __syncthreads();

    if (tid < 64) {
        int run = 0;
#pragma unroll
        for (int ww = 0; ww < 32; ++ww) {
            wbase[ww][tid] = run;
            run += wcnt[ww][tid];
        }
    }
    __syncthreads();

#pragma unroll
    for (int i = 0; i < 8; ++i) {
        int p = i*1024 + tid;
        int prio = wbase[p >> 8][se[p]] + soff[p];
        int tok = g_sorted[grp*T + (p & (T-1))];
        if (p < T) g_prio0[grp*T + tok] = prio; else g_prio1[grp*T + tok] = prio;
    }
    __syncthreads();

    for (int t = tid; t < T; t += 1024) {
        int idx = grp*T + t;
        int e0 = g_e0[idx], e1 = g_e1[idx];
        int pr0 = g_prio0[idx], pr1 = g_prio1[idx];
        float gt0 = g_gate0[idx], gt1 = g_gate1[idx];
        float4 d = make_float4((float)e0, (float)pr0, (float)e1, (float)pr1);
        reinterpret_cast<float4*>(out + DI_OFF)[idx] = d;
        float2 cc = make_float2(pr0 < cap ? gt0 : 0.f, pr1 < cap ? gt1 : 0.f);
        reinterpret_cast<float2*>(out + CW_OFF)[idx] = cc;
    }
}

// ---------------- K4: deterministic per-(g,chunk,e) prob partial sums ----------------
__global__ __launch_bounds__(256) void k4_psum(const float* __restrict__ out) {
    const float* P = out + P_OFF;
    const int grp = blockIdx.x;
    const int ch  = blockIdx.y;
    const int e = threadIdx.x & 63;
    const int q = threadIdx.x >> 6;
    float s = 0.f;
    const int t0 = ch * 512;
    for (int t = t0 + q; t < t0 + 512; t += 4)
        s += P[(size_t)(grp*T + t)*64 + e];
    __shared__ float smr[4][64];
    smr[q][e] = s;
    __syncthreads();
    if (threadIdx.x < 64)
        g_psum2[(grp*8 + ch)*64 + threadIdx.x] =
            smr[0][threadIdx.x] + smr[1][threadIdx.x] +
            smr[2][threadIdx.x] + smr[3][threadIdx.x];
}

// ---------------- K5: final scalars ----------------
__global__ void k5_final(float* __restrict__ out) {
    int lane = threadIdx.x;
    float a = 0.f;
    for (int e = lane; e < 64; e += 32)
        for (int g = 0; g < G; ++g) {
            float ps = 0.f;
#pragma unroll
            for (int ch = 0; ch < 8; ++ch) ps += g_psum2[(g*8 + ch)*64 + e];
            a += (float)g_cnt[g*E + e] * ps;
        }
#pragma unroll
    for (int o = 16; o; o >>= 1) a += __shfl_xor_sync(0xffffffffu, a, o);
    if (lane == 0) {
        float z = 0.f;
        for (int i = 0; i < NCTA; ++i) z += g_zpart[i];
        out[AUX_OFF] = a * (1.f / 2097152.f);
        out[Z_OFF]   = z * (1.f / 32768.f);
    }
}

extern "C" void kernel_launch(void* const* d_in, const int* in_sizes, int n_in,
                              void* d_out, int out_size) {
    const float* X = (const float*)d_in[0];
    const float* W = (const float*)d_in[1];
    const float* B = (const float*)d_in[2];
    const int* cap = (n_in > 3) ? (const int*)d_in[3] : nullptr;
    float* out = (float*)d_out;

    cudaFuncSetAttribute(k1_gemm, cudaFuncAttributeMaxDynamicSharedMemorySize, SMEM_TOTAL);

    k0_prep<<<128, 256>>>(W);
    k1_gemm<<<NCTA, 256, SMEM_TOTAL>>>(X, B, out);
    k2_rank<<<dim3(16, 8), 256>>>();
    k3_prio<<<G, 1024>>>(out, cap);
    k4_psum<<<dim3(8, 8), 256>>>(out);
    k5_final<<<1, 32>>>(out);
}

// round 9
// speedup vs baseline: 1.8034x; 1.0986x over previous
#include <cuda_runtime.h>
#include <cuda_fp16.h>
#include <cstdint>

// Problem constants
#define G 8
#define T 4096
#define H 2048
#define E 64
#define GT (G*T)              // 32768 tokens

// Output layout (float32, concatenated in reference return order)
#define DI_OFF 0              // dispatch_indices [G,T,2,2] -> 131072
#define CW_OFF 131072         // combine_weights  [G,T,2]   -> 65536
#define AUX_OFF 196608        // scalar
#define P_OFF 196609          // router_probs [G,T,64] -> 2097152
#define Z_OFF 2293761         // scalar

// K1 tiling
#define KB 64                 // k-elems per chunk (128B fp16 rows)
#define NCH (H/KB)            // 32 chunks
#define TM 128                // tokens per CTA
#define NCTA (GT/TM)          // 256 CTAs

// dynamic smem byte offsets
#define SO_BS   0                       // bias, 64 floats
#define SO_ZRED 256                     // 4 floats
#define SO_A1   1024                    // x hi limb: 2 bufs x 16KB
#define SO_A2   (SO_A1 + 32768)         // x lo limb (scaled 2^11): 2 bufs x 16KB
#define SO_B1   (SO_A2 + 32768)         // w hi limb: 2 bufs x 8KB
#define SO_B2   (SO_B1 + 16384)         // w lo limb (scaled 2^11): 2 bufs x 8KB
#define SMEM_TOTAL (SO_B2 + 16384)      // 99328 bytes
#define SO_LS   1024                    // epilogue overlay: 128 x 68 floats

#define CORR_SCALE (1.0f/2048.0f)

// -------- scratch (device globals; no allocation allowed) --------
__device__ float g_gate0[GT];
__device__ float g_gate1[GT];
__device__ int   g_e0[GT];
__device__ int   g_e1[GT];
__device__ int   g_sorted[GT];   // packed: tok | e0<<12 | e1<<18 (rank order)
__device__ int   g_prio0[GT];
__device__ int   g_prio1[GT];
__device__ float g_zpart[NCTA];
__device__ int   g_cnt[G*E];
__device__ float g_psum2[NCTA*E];   // per-CTA prob sums (deterministic)
__device__ __half g_w1[E*H];   // W^T hi limb [expert][k]
__device__ __half g_w2[E*H];   // W^T lo limb, scaled by 2^11

__device__ __forceinline__ uint32_t smem_u32(const void* p) {
    uint32_t a;
    asm("{ .reg .u64 t; cvta.to.shared.u64 t, %1; cvt.u32.u64 %0, t; }"
        : "=r"(a) : "l"(p));
    return a;
}
__device__ __forceinline__ void ldsm4(uint32_t* r, uint32_t a) {
    asm volatile("ldmatrix.sync.aligned.m8n8.x4.shared.b16 {%0,%1,%2,%3}, [%4];"
        : "=r"(r[0]), "=r"(r[1]), "=r"(r[2]), "=r"(r[3]) : "r"(a));
}
__device__ __forceinline__ void mma16816(float* c, const uint32_t* a, const uint32_t* b) {
    asm volatile("mma.sync.aligned.m16n8k16.row.col.f32.f16.f16.f32 "
        "{%0,%1,%2,%3}, {%4,%5,%6,%7}, {%8,%9}, {%0,%1,%2,%3};"
        : "+f"(c[0]), "+f"(c[1]), "+f"(c[2]), "+f"(c[3])
        : "r"(a[0]), "r"(a[1]), "r"(a[2]), "r"(a[3]), "r"(b[0]), "r"(b[1]));
}
__device__ __forceinline__ void mma16816h(uint32_t* c, const uint32_t* a, const uint32_t* b) {
    asm volatile("mma.sync.aligned.m16n8k16.row.col.f16.f16.f16.f16 "
        "{%0,%1}, {%2,%3,%4,%5}, {%6,%7}, {%0,%1};"
        : "+r"(c[0]), "+r"(c[1])
        : "r"(a[0]), "r"(a[1]), "r"(a[2]), "r"(a[3]), "r"(b[0]), "r"(b[1]));
}
__device__ __forceinline__ uint32_t h2u(__half2 h) {
    return *reinterpret_cast<uint32_t*>(&h);
}

// ---------------- K0: zero counters + preconvert W^T into fp16 limbs ----------------
__global__ __launch_bounds__(256) void k0_prep(const float* __restrict__ W) {
    int gidx = blockIdx.x * 256 + threadIdx.x;     // 128 CTAs -> 32768 threads
    if (gidx < G*E) g_cnt[gidx] = 0;
    // H*16 float4 granules: k = gidx>>4, experts 4q..4q+3
    int k = gidx >> 4, q = gidx & 15;
    float4 v = reinterpret_cast<const float4*>(W)[gidx];
    float xs[4] = {v.x, v.y, v.z, v.w};
#pragma unroll
    for (int j = 0; j < 4; ++j) {
        int e = 4*q + j;
        __half hi = __float2half_rn(xs[j]);
        float hf = __half2float(hi);
        __half lo = __float2half_rn((xs[j] - hf) * 2048.0f);  // pre-scaled limb
        g_w1[e*H + k] = hi;
        g_w2[e*H + k] = lo;
    }
}

// ---------------- K1: mma.sync GEMM (2-limb fp16, f16-accum corrections) ----------------
// 256 threads (8 warps: 4 M x 2 N), 128 tokens/CTA, chunks of K=64.
// Main pass x1*w1 in fp32 accum; corrections x1*w2' + x2'*w1 (both scaled 2^11)
// in ONE fp16 accumulator at 2x MMA rate; epilogue adds corr * 2^-11.
__global__ __launch_bounds__(256, 2) void k1_gemm(
    const float* __restrict__ X, const float* __restrict__ Bv,
    float* __restrict__ out)
{
    extern __shared__ __align__(16) char smem[];
    __shared__ float psums[4][64];
    const uint32_t sb = smem_u32(smem);
    const int tid = threadIdx.x;
    const int wid = tid >> 5, lane = tid & 31;
    const int wm = wid >> 1, wn = wid & 1;
    const int tok0 = blockIdx.x * TM;

    if (tid < 64) *reinterpret_cast<float*>(smem + SO_BS + tid*4) = Bv[tid];

    float acc[2][4][4];
    uint32_t acch[2][4][2];
#pragma unroll
    for (int mt = 0; mt < 2; ++mt)
#pragma unroll
        for (int nt = 0; nt < 4; ++nt) {
#pragma unroll
            for (int i = 0; i < 4; ++i) acc[mt][nt][i] = 0.f;
            acch[mt][nt][0] = 0u; acch[mt][nt][1] = 0u;
        }

    float4 xv[8];

    auto ldg_chunk = [&](int ch) {
        const int hc = ch * KB;
#pragma unroll
        for (int it = 0; it < 8; ++it) {
            int idx = it*256 + tid, row = idx >> 4, q = idx & 15;
            xv[it] = *reinterpret_cast<const float4*>(
                X + (size_t)(tok0 + row)*H + hc + q*4);
        }
    };

    auto sts_chunk = [&](int ch, int buf) {
        const int hc = ch * KB;
        char* A1 = smem + SO_A1 + buf*16384;
        char* A2 = smem + SO_A2 + buf*16384;
#pragma unroll
        for (int it = 0; it < 8; ++it) {
            int idx = it*256 + tid, row = idx >> 4, q = idx & 15;
            float4 v = xv[it];
            __half2 h01 = __floats2half2_rn(v.x, v.y);
            __half2 h23 = __floats2half2_rn(v.z, v.w);
            float2 f01 = __half22float2(h01);
            float2 f23 = __half22float2(h23);
            __half2 l01 = __floats2half2_rn((v.x - f01.x)*2048.f, (v.y - f01.y)*2048.f);
            __half2 l23 = __floats2half2_rn((v.z - f23.x)*2048.f, (v.w - f23.y)*2048.f);
            int offs = row*128 + ((((q >> 1) ^ (row & 7)) << 4) | ((q & 1) << 3));
            *reinterpret_cast<uint2*>(A1 + offs) = make_uint2(h2u(h01), h2u(h23));
            *reinterpret_cast<uint2*>(A2 + offs) = make_uint2(h2u(l01), h2u(l23));
        }
        // W loaded inline (L2-resident; no long-lived staging regs)
        char* B1 = smem + SO_B1 + buf*8192;
        char* B2 = smem + SO_B2 + buf*8192;
#pragma unroll
        for (int it = 0; it < 2; ++it) {
            int idx = it*256 + tid, e = idx >> 3, g = idx & 7;
            uint4 w1v = reinterpret_cast<const uint4*>(g_w1 + (size_t)e*H + hc)[g];
            uint4 w2v = reinterpret_cast<const uint4*>(g_w2 + (size_t)e*H + hc)[g];
            int offs = e*128 + ((g ^ (e & 7)) << 4);
            *reinterpret_cast<uint4*>(B1 + offs) = w1v;
            *reinterpret_cast<uint4*>(B2 + offs) = w2v;
        }
    };

    auto comp_chunk = [&](int buf) {
        const uint32_t sA1 = sb + SO_A1 + buf*16384;
        const uint32_t sB1 = sb + SO_B1 + buf*8192;
#pragma unroll
        for (int ks = 0; ks < 4; ++ks) {
            const int kb = ks*2;
            uint32_t a1f[2][4], a2f[2][4], b1f[2][4], b2f[2][4];
#pragma unroll
            for (int mt = 0; mt < 2; ++mt) {
                int row = wm*32 + mt*16 + (lane & 15);
                int col = (kb + (lane >> 4)) ^ (row & 7);
                uint32_t ad = sA1 + row*128 + col*16;
                ldsm4(a1f[mt], ad);
                ldsm4(a2f[mt], ad + (SO_A2 - SO_A1));
            }
#pragma unroll
            for (int ng = 0; ng < 2; ++ng) {
                int rowb = wn*32 + ng*16 + (lane & 7) + ((lane >> 4) << 3);
                int colb = (kb + ((lane >> 3) & 1)) ^ (rowb & 7);
                uint32_t bd = sB1 + rowb*128 + colb*16;
                ldsm4(b1f[ng], bd);
                ldsm4(b2f[ng], bd + (SO_B2 - SO_B1));
            }
#pragma unroll
            for (int mt = 0; mt < 2; ++mt)
#pragma unroll
                for (int ng = 0; ng < 2; ++ng)
#pragma unroll
                    for (int hf = 0; hf < 2; ++hf) {
                        float* c = acc[mt][ng*2 + hf];
                        uint32_t* ch = acch[mt][ng*2 + hf];
                        mma16816(c, a1f[mt], &b1f[ng][hf*2]);
                        mma16816h(ch, a1f[mt], &b2f[ng][hf*2]);
                        mma16816h(ch, a2f[mt], &b1f[ng][hf*2]);
                    }
        }
    };

    ldg_chunk(0);
    sts_chunk(0, 0);
#pragma unroll 1
    for (int ch = 0; ch < NCH; ++ch) {
        if (ch + 1 < NCH) ldg_chunk(ch + 1);
        __syncthreads();
        comp_chunk(ch & 1);
        if (ch + 1 < NCH) sts_chunk(ch + 1, (ch + 1) & 1);
    }
    __syncthreads();   // all comp done; safe to overlay ls

    // ---- dump accumulators (+ scaled corrections) to ls[128][68] ----
    float* ls = reinterpret_cast<float*>(smem + SO_LS);
#pragma unroll
    for (int mt = 0; mt < 2; ++mt)
#pragma unroll
        for (int nt = 0; nt < 4; ++nt) {
            int row = wm*32 + mt*16 + (lane >> 2);
            int col = wn*32 + nt*8 + (lane & 3)*2;
            __half2 hc0 = *reinterpret_cast<__half2*>(&acch[mt][nt][0]);
            __half2 hc1 = *reinterpret_cast<__half2*>(&acch[mt][nt][1]);
            float2 c01 = __half22float2(hc0);
            float2 c23 = __half22float2(hc1);
            *reinterpret_cast<float2*>(ls + row*68 + col) =
                make_float2(acc[mt][nt][0] + c01.x*CORR_SCALE,
                            acc[mt][nt][1] + c01.y*CORR_SCALE);
            *reinterpret_cast<float2*>(ls + (row + 8)*68 + col) =
                make_float2(acc[mt][nt][2] + c23.x*CORR_SCALE,
                            acc[mt][nt][3] + c23.y*CORR_SCALE);
        }
    __syncthreads();

    // ---- per-token epilogue (warps 0-3, 1 token per thread) ----
    float* bs = reinterpret_cast<float*>(smem + SO_BS);
    float* zred = reinterpret_cast<float*>(smem + SO_ZRED);
    float lg[64];
    float zl = 0.f;
    if (tid < 128) {
        const int t = tid;
#pragma unroll
        for (int e = 0; e < 64; ++e) lg[e] = ls[t*68 + e] + bs[e];

        float mx = lg[0];
#pragma unroll
        for (int e = 1; e < 64; ++e) mx = fmaxf(mx, lg[e]);
        float ssum = 0.f;
#pragma unroll
        for (int e = 0; e < 64; ++e) { float p = expf(lg[e] - mx); lg[e] = p; ssum += p; }
        float logz = mx + logf(ssum);
        float inv = 1.f / ssum;
#pragma unroll
        for (int e = 0; e < 64; ++e) lg[e] *= inv;

        float p0 = -1.f, p1 = -1.f; int i0 = 0, i1 = 0;
#pragma unroll
        for (int e = 0; e < 64; ++e) {
            float v = lg[e];
            if (v > p0) { p1 = p0; i1 = i0; p0 = v; i0 = e; }
            else if (v > p1) { p1 = v; i1 = e; }
        }
        const int token = tok0 + t;
        g_gate0[token] = p0; g_gate1[token] = p1;
        g_e0[token] = i0;    g_e1[token] = i1;
        const int grp = token >> 12;
        atomicAdd(&g_cnt[grp*E + i0], 1);
        atomicAdd(&g_cnt[grp*E + i1], 1);
        zl = logz * logz;
    }
    __syncthreads();

    if (tid < 128) {
        // probs back into ls
        float* row = ls + tid*68;
#pragma unroll
        for (int c = 0; c < 16; ++c)
            *reinterpret_cast<float4*>(row + c*4) =
                make_float4(lg[4*c], lg[4*c+1], lg[4*c+2], lg[4*c+3]);
#pragma unroll
        for (int o = 16; o; o >>= 1) zl += __shfl_xor_sync(0xffffffffu, zl, o);
        if (lane == 0) zred[wid] = zl;
    }
    __syncthreads();

    // coalesced prob copy-out + deterministic per-CTA per-expert sums
    // (expert id k&63 is invariant under stride 256)
    float* P = out + P_OFF + (size_t)tok0*64;
    float s = 0.f;
    for (int k = tid; k < TM*64; k += 256) {
        float v = ls[(k >> 6)*68 + (k & 63)];
        P[k] = v;
        s += v;
    }
    psums[tid >> 6][tid & 63] = s;
    __syncthreads();
    if (tid < 64)
        g_psum2[blockIdx.x*64 + tid] =
            psums[0][tid] + psums[1][tid] + psums[2][tid] + psums[3][tid];

    if (tid == 0)
        g_zpart[blockIdx.x] = zred[0] + zred[1] + zred[2] + zred[3];
}

// ---------------- K2: stable rank by gate0 (descending), pack tok+experts ----------------
__global__ __launch_bounds__(256) void k2_rank() {
    __shared__ float gs[T];
    const int tid = threadIdx.x;
    const int grp = blockIdx.y;
    for (int i = tid; i < T; i += 256) gs[i] = g_gate0[grp*T + i];
    __syncthreads();
    const int t = blockIdx.x * 256 + tid;
    const float gi = gs[t];
    int rank = 0;
#pragma unroll 8
    for (int j = 0; j < T; ++j) {
        float gj = gs[j];
        rank += (gj > gi) || (gj == gi && j < t);
    }
    int e0 = g_e0[grp*T + t], e1 = g_e1[grp*T + t];
    g_sorted[grp*T + rank] = t | (e0 << 12) | (e1 << 18);
}

// ---------------- K3: expert buffer priorities + dispatch/combine ----------------
// 1024 threads; sequential packed load (no random gathers), 32 warp segments,
// warp-local running counts, exclusive scan over warp histograms, scatter.
__global__ __launch_bounds__(1024) void k3_prio(float* __restrict__ out, const int* __restrict__ capPtr) {
    __shared__ unsigned char se[2*T];
    __shared__ unsigned char soff[2*T];
    __shared__ short stok[T];
    __shared__ int wcnt[32][64];
    __shared__ int wbase[32][64];

    const int tid = threadIdx.x;
    const int grp = blockIdx.x;
    const int cap = capPtr ? *capPtr : 160;
    const int w = tid >> 5, lane = tid & 31;
    const unsigned lt = (1u << lane) - 1u;

    wcnt[w][lane] = 0;
    wcnt[w][lane + 32] = 0;

    // sequential packed load: one coalesced pass fills tok, e0, e1
    for (int p = tid; p < T; p += 1024) {
        int pk = g_sorted[grp*T + p];
        stok[p] = (short)(pk & 4095);
        se[p]     = (unsigned char)((pk >> 12) & 63);
        se[p + T] = (unsigned char)((pk >> 18) & 63);
    }
    __syncthreads();

    // warp-sequential running counts over 8 sub-chunks of each 256-segment
#pragma unroll
    for (int i = 0; i < 8; ++i) {
        int p = w*256 + i*32 + lane;
        int e = se[p];
        unsigned m = __match_any_sync(0xffffffffu, e);
        int lrank = __popc(m & lt);
        int off = wcnt[w][e] + lrank;
        soff[p] = (unsigned char)off;
        __syncwarp();
        if (lane == (__ffs(m) - 1)) wcnt[w][e] += __popc(m);
        __syncwarp();
    }
    __syncthreads();

    // exclusive scan over warps, per expert
    if (tid < 64) {
        int run = 0;
#pragma unroll
        for (int ww = 0; ww < 32; ++ww) {
            wbase[ww][tid] = run;
            run += wcnt[ww][tid];
        }
    }
    __syncthreads();

    // scatter priorities back to token order
#pragma unroll
    for (int i = 0; i < 8; ++i) {
        int p = i*1024 + tid;
        int prio = wbase[p >> 8][se[p]] + soff[p];
        int tok = stok[p & (T-1)];
        if (p < T) g_prio0[grp*T + tok] = prio; else g_prio1[grp*T + tok] = prio;
    }
    __syncthreads();

    // final per-token outputs for this group
    for (int t = tid; t < T; t += 1024) {
        int idx = grp*T + t;
        int e0 = g_e0[idx], e1 = g_e1[idx];
        int pr0 = g_prio0[idx], pr1 = g_prio1[idx];
        float gt0 = g_gate0[idx], gt1 = g_gate1[idx];
        float4 d = make_float4((float)e0, (float)pr0, (float)e1, (float)pr1);
        reinterpret_cast<float4*>(out + DI_OFF)[idx] = d;
        float2 cc = make_float2(pr0 < cap ? gt0 : 0.f, pr1 < cap ? gt1 : 0.f);
        reinterpret_cast<float2*>(out + CW_OFF)[idx] = cc;
    }
}

// ---------------- K5: final scalars (deterministic reduction of per-CTA sums) ----------------
__global__ __launch_bounds__(512) void k5_final(float* __restrict__ out) {
    __shared__ float red[16];
    const int tid = threadIdx.x;       // 512 = 8 groups x 64 experts
    const int g = tid >> 6, e = tid & 63;
    float ps = 0.f;
#pragma unroll
    for (int c = 0; c < 32; ++c) ps += g_psum2[(g*32 + c)*64 + e];
    float a = (float)g_cnt[g*E + e] * ps;
#pragma unroll
    for (int o = 16; o; o >>= 1) a += __shfl_xor_sync(0xffffffffu, a, o);
    if ((tid & 31) == 0) red[tid >> 5] = a;
    __syncthreads();
    if (tid == 0) {
        float s = 0.f;
#pragma unroll
        for (int i = 0; i < 16; ++i) s += red[i];
        float z = 0.f;
        for (int i = 0; i < NCTA; ++i) z += g_zpart[i];
        out[AUX_OFF] = s * (1.f / 2097152.f);
        out[Z_OFF]   = z * (1.f / 32768.f);
    }
}

extern "C" void kernel_launch(void* const* d_in, const int* in_sizes, int n_in,
                              void* d_out, int out_size) {
    const float* X = (const float*)d_in[0];
    const float* W = (const float*)d_in[1];
    const float* B = (const float*)d_in[2];
    const int* cap = (n_in > 3) ? (const int*)d_in[3] : nullptr;
    float* out = (float*)d_out;

    cudaFuncSetAttribute(k1_gemm, cudaFuncAttributeMaxDynamicSharedMemorySize, SMEM_TOTAL);

    k0_prep<<<128, 256>>>(W);
    k1_gemm<<<NCTA, 256, SMEM_TOTAL>>>(X, B, out);
    k2_rank<<<dim3(16, 8), 256>>>();
    k3_prio<<<G, 1024>>>(out, cap);
    k5_final<<<1, 512>>>(out);
}